// round 8
// baseline (speedup 1.0000x reference)
#include <cuda_runtime.h>
#include <cuda_fp16.h>
#include <cstdint>

#define N_B     4
#define C_DIM   128
#define HW      4096
#define NT      32              // s-tiles of 128
#define RSTRIDE 136             // halves per row (272B, conflict-free ldmatrix)
#define THREADS 256

// fp16 images: Q/K hi+lo [token][c]; V single [tile][e][s]
__device__ __align__(16) __half g_q_h[N_B * HW * RSTRIDE];
__device__ __align__(16) __half g_q_l[N_B * HW * RSTRIDE];
__device__ __align__(16) __half g_k_h[N_B * HW * RSTRIDE];
__device__ __align__(16) __half g_k_l[N_B * HW * RSTRIDE];
__device__ __align__(16) __half g_v_h[N_B * NT * C_DIM * RSTRIDE];

#define TILE_BYTES (128 * RSTRIDE * 2)   // 34816

// ---------------------------------------------------------------------------
__device__ __forceinline__ uint32_t smem_u32(const void* p) {
    uint32_t a;
    asm("{ .reg .u64 t; cvta.to.shared.u64 t, %1; cvt.u32.u64 %0, t; }" : "=r"(a) : "l"(p));
    return a;
}
__device__ __forceinline__ float ex2f(float x) {
    float y; asm("ex2.approx.ftz.f32 %0, %1;" : "=f"(y) : "f"(x)); return y;
}
__device__ __forceinline__ void cpa16(uint32_t d, const void* s) {
    asm volatile("cp.async.cg.shared.global [%0], [%1], 16;" :: "r"(d), "l"(s));
}
__device__ __forceinline__ void cp_commit() { asm volatile("cp.async.commit_group;"); }
__device__ __forceinline__ void cp_wait0()  { asm volatile("cp.async.wait_group 0;" ::: "memory"); }
__device__ __forceinline__ void cp_wait1()  { asm volatile("cp.async.wait_group 1;" ::: "memory"); }

__device__ __forceinline__ void ldsm4(uint32_t* r, uint32_t addr) {
    asm volatile("ldmatrix.sync.aligned.m8n8.x4.shared.b16 {%0,%1,%2,%3}, [%4];"
                 : "=r"(r[0]), "=r"(r[1]), "=r"(r[2]), "=r"(r[3]) : "r"(addr));
}
__device__ __forceinline__ void mma_f16(float* d, const uint32_t* a, uint32_t b0, uint32_t b1) {
    asm volatile("mma.sync.aligned.m16n8k16.row.col.f32.f16.f16.f32 "
                 "{%0,%1,%2,%3}, {%4,%5,%6,%7}, {%8,%9}, {%0,%1,%2,%3};"
                 : "+f"(d[0]), "+f"(d[1]), "+f"(d[2]), "+f"(d[3])
                 : "r"(a[0]), "r"(a[1]), "r"(a[2]), "r"(a[3]), "r"(b0), "r"(b1));
}

// ---------------------------------------------------------------------------
// Prep (one launch): z=0 Q, z=1 K (transpose to [token][c], fp16 hi/lo);
//                    z=2 V (native [e][s], fp16 single).
// ---------------------------------------------------------------------------
__global__ void prep_all(const float* __restrict__ q, const float* __restrict__ k,
                         const float* __restrict__ v) {
    extern __shared__ float sm[];                  // [128][129]
    int tb = blockIdx.x, n = blockIdx.y, z = blockIdx.z;
    if (z < 2) {
        const float* src = (z ? k : q) + (size_t)n * C_DIM * HW + tb * 128;
        __half* gh = (z ? g_k_h : g_q_h) + (size_t)(n * HW + tb * 128) * RSTRIDE;
        __half* gl = (z ? g_k_l : g_q_l) + (size_t)(n * HW + tb * 128) * RSTRIDE;
        for (int i = threadIdx.x; i < 16384; i += THREADS) {
            int c = i >> 7, t = i & 127;
            sm[c * 129 + t] = src[(size_t)c * HW + t];
        }
        __syncthreads();
        for (int i = threadIdx.x; i < 16384; i += THREADS) {
            int t = i >> 7, c = i & 127;
            float val = sm[c * 129 + t];
            __half h = __float2half_rn(val);
            gh[(size_t)t * RSTRIDE + c] = h;
            gl[(size_t)t * RSTRIDE + c] = __float2half_rn(val - __half2float(h));
        }
    } else {
        const float* src = v + (size_t)n * C_DIM * HW + tb * 128;
        __half* gh = g_v_h + (size_t)(n * NT + tb) * C_DIM * RSTRIDE;
        for (int i = threadIdx.x; i < 16384; i += THREADS) {
            int e = i >> 7, s = i & 127;
            gh[(size_t)e * RSTRIDE + s] = __float2half_rn(src[(size_t)e * HW + s]);
        }
    }
}

// ---------------------------------------------------------------------------
// Fused flash attention, fp16 HMMA, no-max softmax, double-buffered V.
// ---------------------------------------------------------------------------
#define SM_Q_HI 0
#define SM_Q_LO 34816
#define SM_K_HI 69632
#define SM_K_LO 104448
#define SM_V0   139264
#define SM_V1   174080
#define SM_REQ  (208896 + 1024)

__global__ __launch_bounds__(THREADS, 1)
void attn_kernel(float* __restrict__ out) {
    extern __shared__ char smraw[];
    uint32_t raw = smem_u32(smraw);
    uint32_t base = (raw + 1023u) & ~1023u;

    const int tid = threadIdx.x, wid = tid >> 5, lane = tid & 31;
    const int n = blockIdx.y, tb = blockIdx.x;
    const int t0 = wid * 16;

    // prologue: Q(hi,lo) + K0(hi,lo) + V0 — one commit group
    {
        const char* gq_h = (const char*)(g_q_h + (size_t)(n * HW + tb * 128) * RSTRIDE);
        const char* gq_l = (const char*)(g_q_l + (size_t)(n * HW + tb * 128) * RSTRIDE);
        const char* gk_h = (const char*)(g_k_h + (size_t)(n * HW) * RSTRIDE);
        const char* gk_l = (const char*)(g_k_l + (size_t)(n * HW) * RSTRIDE);
        const char* gv   = (const char*)(g_v_h + (size_t)(n * NT) * C_DIM * RSTRIDE);
        for (int i = tid; i < TILE_BYTES / 16; i += THREADS) {
            cpa16(base + SM_Q_HI + i * 16, gq_h + i * 16);
            cpa16(base + SM_Q_LO + i * 16, gq_l + i * 16);
            cpa16(base + SM_K_HI + i * 16, gk_h + i * 16);
            cpa16(base + SM_K_LO + i * 16, gk_l + i * 16);
            cpa16(base + SM_V0   + i * 16, gv   + i * 16);
        }
        cp_commit();
    }

    const uint32_t rb  = (uint32_t)(lane & 15) * 272 + ((uint32_t)(lane >> 4) << 4);
    const uint32_t aQh = base + SM_Q_HI + (uint32_t)t0 * 272 + rb;
    const uint32_t aQl = base + SM_Q_LO + (uint32_t)t0 * 272 + rb;
    const uint32_t bKh = base + SM_K_HI + rb;
    const uint32_t bKl = base + SM_K_LO + rb;

    const float SCALE = 1.44269504088896340736f * 0.08838834764831844f; // log2e/sqrt(128)

    float O[16][4];
    float ls0 = 0.f, ls1 = 0.f;
#pragma unroll
    for (int j = 0; j < 16; j++)
#pragma unroll
        for (int q = 0; q < 4; q++) O[j][q] = 0.f;

    for (int it = 0; it < NT; it++) {
        __syncthreads();    // prior GEMM2 done reading V[(it+1)&1]'s buffer
        if (it + 1 < NT) {  // prefetch V(it+1) into alternate buffer (fully hidden)
            const char* nv = (const char*)(g_v_h + (size_t)(n * NT + it + 1) * C_DIM * RSTRIDE);
            uint32_t dst = base + (((it + 1) & 1) ? SM_V1 : SM_V0);
            for (int i = tid; i < TILE_BYTES / 16; i += THREADS)
                cpa16(dst + i * 16, nv + i * 16);
            cp_commit();
            cp_wait1();      // K(it), V(it) complete; V(it+1) in flight
        } else {
            cp_wait0();
        }
        __syncthreads();

        // ---- GEMM1: S = Q·K^T, fp16 3-combo (qh·kh + qh·kl + ql·kh) ----
        float S[16][4];
#pragma unroll
        for (int j = 0; j < 16; j++)
#pragma unroll
            for (int q = 0; q < 4; q++) S[j][q] = 0.f;

#pragma unroll
        for (int kc = 0; kc < 8; kc++) {
            uint32_t qh[4], ql[4];
            ldsm4(qh, aQh + kc * 32);
            ldsm4(ql, aQl + kc * 32);
#pragma unroll
            for (int sp = 0; sp < 8; sp++) {
                uint32_t kh[4], kl[4];
                ldsm4(kh, bKh + sp * 4352 + kc * 32);
                ldsm4(kl, bKl + sp * 4352 + kc * 32);
                mma_f16(S[2 * sp],     qh, kh[0], kh[2]);
                mma_f16(S[2 * sp + 1], qh, kh[1], kh[3]);
                mma_f16(S[2 * sp],     qh, kl[0], kl[2]);
                mma_f16(S[2 * sp + 1], qh, kl[1], kl[3]);
                mma_f16(S[2 * sp],     ql, kh[0], kh[2]);
                mma_f16(S[2 * sp + 1], ql, kh[1], kh[3]);
            }
        }

        __syncthreads();                      // all warps done reading K
        if (it + 1 < NT) {                    // prefetch K(it+1), hidden by softmax+GEMM2
            const char* nk_h = (const char*)(g_k_h + (size_t)(n * HW + (it + 1) * 128) * RSTRIDE);
            const char* nk_l = (const char*)(g_k_l + (size_t)(n * HW + (it + 1) * 128) * RSTRIDE);
            for (int i = tid; i < TILE_BYTES / 16; i += THREADS) {
                cpa16(base + SM_K_HI + i * 16, nk_h + i * 16);
                cpa16(base + SM_K_LO + i * 16, nk_l + i * 16);
            }
            cp_commit();
        }

        // ---- softmax (no max): P = exp2(S*SCALE) ----
#pragma unroll
        for (int j = 0; j < 16; j++) {
            float p0 = ex2f(S[j][0] * SCALE);
            float p1 = ex2f(S[j][1] * SCALE);
            float p2 = ex2f(S[j][2] * SCALE);
            float p3 = ex2f(S[j][3] * SCALE);
            S[j][0] = p0; S[j][1] = p1; S[j][2] = p2; S[j][3] = p3;
            ls0 += p0 + p1;
            ls1 += p2 + p3;
        }

        // ---- GEMM2: O += P·V^T, P split fp16 hi/lo, V single fp16 ----
        const uint32_t bV = base + ((it & 1) ? SM_V1 : SM_V0) + rb;
#pragma unroll
        for (int ks = 0; ks < 8; ks++) {
            const float* pj0 = S[2 * ks];
            const float* pj1 = S[2 * ks + 1];
            uint32_t ph[4], pl[4];
            {
                __half2 h, l;
                h = __floats2half2_rn(pj0[0], pj0[1]); ph[0] = *(uint32_t*)&h;
                l = __floats2half2_rn(pj0[0] - __low2float(h), pj0[1] - __high2float(h)); pl[0] = *(uint32_t*)&l;
                h = __floats2half2_rn(pj0[2], pj0[3]); ph[1] = *(uint32_t*)&h;
                l = __floats2half2_rn(pj0[2] - __low2float(h), pj0[3] - __high2float(h)); pl[1] = *(uint32_t*)&l;
                h = __floats2half2_rn(pj1[0], pj1[1]); ph[2] = *(uint32_t*)&h;
                l = __floats2half2_rn(pj1[0] - __low2float(h), pj1[1] - __high2float(h)); pl[2] = *(uint32_t*)&l;
                h = __floats2half2_rn(pj1[2], pj1[3]); ph[3] = *(uint32_t*)&h;
                l = __floats2half2_rn(pj1[2] - __low2float(h), pj1[3] - __high2float(h)); pl[3] = *(uint32_t*)&l;
            }
#pragma unroll
            for (int ep = 0; ep < 8; ep++) {
                uint32_t vh[4];
                ldsm4(vh, bV + ep * 4352 + ks * 32);
                mma_f16(O[2 * ep],     ph, vh[0], vh[2]);
                mma_f16(O[2 * ep + 1], ph, vh[1], vh[3]);
                mma_f16(O[2 * ep],     pl, vh[0], vh[2]);
                mma_f16(O[2 * ep + 1], pl, vh[1], vh[3]);
            }
        }
    }

    // ---- epilogue ----
    ls0 += __shfl_xor_sync(0xFFFFFFFFu, ls0, 1);
    ls0 += __shfl_xor_sync(0xFFFFFFFFu, ls0, 2);
    ls1 += __shfl_xor_sync(0xFFFFFFFFu, ls1, 1);
    ls1 += __shfl_xor_sync(0xFFFFFFFFu, ls1, 2);
    float inv0 = __frcp_rn(ls0);
    float inv1 = __frcp_rn(ls1);

    __syncthreads();
    float* smT = (float*)(smraw + (base - raw) + SM_K_HI);   // [128][136] f32
    {
        int trow = t0 + (lane >> 2);
#pragma unroll
        for (int j = 0; j < 16; j++) {
            int e0 = j * 8 + (lane & 3) * 2;
            smT[e0 * RSTRIDE + trow]           = O[j][0] * inv0;
            smT[(e0 + 1) * RSTRIDE + trow]     = O[j][1] * inv0;
            smT[e0 * RSTRIDE + trow + 8]       = O[j][2] * inv1;
            smT[(e0 + 1) * RSTRIDE + trow + 8] = O[j][3] * inv1;
        }
    }
    __syncthreads();
    float* ob = out + (size_t)n * C_DIM * HW + tb * 128;
    for (int i = tid; i < 128 * 32; i += THREADS) {
        int e = i >> 5, q4 = (i & 31) * 4;
        *(float4*)(ob + (size_t)e * HW + q4) = *(float4*)(smT + e * RSTRIDE + q4);
    }
}

// ---------------------------------------------------------------------------
extern "C" void kernel_launch(void* const* d_in, const int* in_sizes, int n_in,
                              void* d_out, int out_size) {
    const float* key   = (const float*)d_in[0];
    const float* query = (const float*)d_in[1];
    const float* value = (const float*)d_in[2];
    float* out = (float*)d_out;

    cudaFuncSetAttribute(prep_all, cudaFuncAttributeMaxDynamicSharedMemorySize, 66048);
    cudaFuncSetAttribute(attn_kernel, cudaFuncAttributeMaxDynamicSharedMemorySize, SM_REQ);

    prep_all<<<dim3(NT, N_B, 3), THREADS, 66048>>>(query, key, value);
    attn_kernel<<<dim3(NT, N_B), THREADS, SM_REQ>>>(out);
}

// round 9
// speedup vs baseline: 3.3811x; 3.3811x over previous
#include <cuda_runtime.h>
#include <cuda_fp16.h>
#include <cstdint>

#define N_B     4
#define C_DIM   128
#define HW      4096
#define NT      32              // s-tiles of 128
#define RSTRIDE 136             // halves per row (272B, conflict-free ldmatrix)
#define THREADS 256

// fp16 images (single precision): Q[t][c], K[s][c], V tile-blocked [tile][e][s]
__device__ __align__(16) __half g_q[N_B * HW * RSTRIDE];
__device__ __align__(16) __half g_k[N_B * HW * RSTRIDE];
__device__ __align__(16) __half g_v[N_B * NT * C_DIM * RSTRIDE];

#define TILE_BYTES (128 * RSTRIDE * 2)   // 34816

// ---------------------------------------------------------------------------
__device__ __forceinline__ uint32_t smem_u32(const void* p) {
    uint32_t a;
    asm("{ .reg .u64 t; cvta.to.shared.u64 t, %1; cvt.u32.u64 %0, t; }" : "=r"(a) : "l"(p));
    return a;
}
__device__ __forceinline__ float ex2f(float x) {
    float y; asm("ex2.approx.ftz.f32 %0, %1;" : "=f"(y) : "f"(x)); return y;
}
__device__ __forceinline__ void cpa16(uint32_t d, const void* s) {
    asm volatile("cp.async.cg.shared.global [%0], [%1], 16;" :: "r"(d), "l"(s));
}
__device__ __forceinline__ void cp_commit() { asm volatile("cp.async.commit_group;"); }
__device__ __forceinline__ void cp_wait0()  { asm volatile("cp.async.wait_group 0;" ::: "memory"); }

__device__ __forceinline__ void ldsm4(uint32_t* r, uint32_t addr) {
    asm volatile("ldmatrix.sync.aligned.m8n8.x4.shared.b16 {%0,%1,%2,%3}, [%4];"
                 : "=r"(r[0]), "=r"(r[1]), "=r"(r[2]), "=r"(r[3]) : "r"(addr));
}
__device__ __forceinline__ void mma_f16(float* d, const uint32_t* a, uint32_t b0, uint32_t b1) {
    asm volatile("mma.sync.aligned.m16n8k16.row.col.f32.f16.f16.f32 "
                 "{%0,%1,%2,%3}, {%4,%5,%6,%7}, {%8,%9}, {%0,%1,%2,%3};"
                 : "+f"(d[0]), "+f"(d[1]), "+f"(d[2]), "+f"(d[3])
                 : "r"(a[0]), "r"(a[1]), "r"(a[2]), "r"(a[3]), "r"(b0), "r"(b1));
}

// ---------------------------------------------------------------------------
// Prep: z=0 Q, z=1 K (transpose to [token][c]); z=2 V (native [e][s]).
// ---------------------------------------------------------------------------
__global__ void prep_all(const float* __restrict__ q, const float* __restrict__ k,
                         const float* __restrict__ v) {
    extern __shared__ float sm[];                  // [128][129]
    int tb = blockIdx.x, n = blockIdx.y, z = blockIdx.z;
    if (z < 2) {
        const float* src = (z ? k : q) + (size_t)n * C_DIM * HW + tb * 128;
        __half* gh = (z ? g_k : g_q) + (size_t)(n * HW + tb * 128) * RSTRIDE;
        for (int i = threadIdx.x; i < 16384; i += THREADS) {
            int c = i >> 7, t = i & 127;
            sm[c * 129 + t] = src[(size_t)c * HW + t];
        }
        __syncthreads();
        for (int i = threadIdx.x; i < 8192; i += THREADS) {
            int t = i >> 6, c2 = (i & 63) * 2;
            __half2 h = __floats2half2_rn(sm[c2 * 129 + t], sm[(c2 + 1) * 129 + t]);
            *(__half2*)(gh + (size_t)t * RSTRIDE + c2) = h;
        }
    } else {
        const float* src = v + (size_t)n * C_DIM * HW + tb * 128;
        __half* gh = g_v + (size_t)(n * NT + tb) * C_DIM * RSTRIDE;
        for (int i = threadIdx.x; i < 8192; i += THREADS) {
            int e = i >> 6, s2 = (i & 63) * 2;
            const float* p = src + (size_t)e * HW + s2;
            *(__half2*)(gh + (size_t)e * RSTRIDE + s2) = __floats2half2_rn(p[0], p[1]);
        }
    }
}

// ---------------------------------------------------------------------------
// Fused flash attention: fp16 HMMA, no-max softmax, K+V double buffered.
// ---------------------------------------------------------------------------
#define SM_Q  0
#define SM_K0 34816
#define SM_K1 69632
#define SM_V0 104448
#define SM_V1 139264
#define SM_REQ (174080 + 1024)

__global__ __launch_bounds__(THREADS, 1)
void attn_kernel(float* __restrict__ out) {
    extern __shared__ char smraw[];
    uint32_t raw = smem_u32(smraw);
    uint32_t base = (raw + 1023u) & ~1023u;

    const int tid = threadIdx.x, wid = tid >> 5, lane = tid & 31;
    const int n = blockIdx.y, tb = blockIdx.x;
    const int t0 = wid * 16;

    // prologue: Q + K0 + V0, one group
    {
        const char* gq = (const char*)(g_q + (size_t)(n * HW + tb * 128) * RSTRIDE);
        const char* gk = (const char*)(g_k + (size_t)(n * HW) * RSTRIDE);
        const char* gv = (const char*)(g_v + (size_t)(n * NT) * C_DIM * RSTRIDE);
        for (int i = tid; i < TILE_BYTES / 16; i += THREADS) {
            cpa16(base + SM_Q  + i * 16, gq + i * 16);
            cpa16(base + SM_K0 + i * 16, gk + i * 16);
            cpa16(base + SM_V0 + i * 16, gv + i * 16);
        }
        cp_commit();
    }

    const uint32_t rb = (uint32_t)(lane & 15) * 272 + ((uint32_t)(lane >> 4) << 4);
    const uint32_t aQ = base + SM_Q + (uint32_t)t0 * 272 + rb;

    const float SCALE = 1.44269504088896340736f * 0.08838834764831844f; // log2e/sqrt(128)

    float O[16][4];
    float ls0 = 0.f, ls1 = 0.f;
#pragma unroll
    for (int j = 0; j < 16; j++)
#pragma unroll
        for (int q = 0; q < 4; q++) O[j][q] = 0.f;

    for (int it = 0; it < NT; it++) {
        cp_wait0();          // K(it), V(it) resident (prefetched one iter ago)
        __syncthreads();     // all warps done reading the buffers being overwritten

        if (it + 1 < NT) {   // prefetch next K,V into alternate buffers (fully hidden)
            const char* nk = (const char*)(g_k + (size_t)(n * HW + (it + 1) * 128) * RSTRIDE);
            const char* nv = (const char*)(g_v + (size_t)(n * NT + it + 1) * C_DIM * RSTRIDE);
            uint32_t dk = base + (((it + 1) & 1) ? SM_K1 : SM_K0);
            uint32_t dv = base + (((it + 1) & 1) ? SM_V1 : SM_V0);
            for (int i = tid; i < TILE_BYTES / 16; i += THREADS) {
                cpa16(dk + i * 16, nk + i * 16);
                cpa16(dv + i * 16, nv + i * 16);
            }
            cp_commit();
        }

        const uint32_t bK = base + ((it & 1) ? SM_K1 : SM_K0) + rb;
        const uint32_t bV = base + ((it & 1) ? SM_V1 : SM_V0) + rb;

        // ---- GEMM1: S[t][s] = Q[t][c] · K[s][c]^T ----
        float S[16][4];
#pragma unroll
        for (int j = 0; j < 16; j++)
#pragma unroll
            for (int q = 0; q < 4; q++) S[j][q] = 0.f;

#pragma unroll
        for (int kc = 0; kc < 8; kc++) {
            uint32_t qf[4];
            ldsm4(qf, aQ + kc * 32);
#pragma unroll
            for (int sp = 0; sp < 8; sp++) {
                uint32_t kf[4];
                ldsm4(kf, bK + sp * 4352 + kc * 32);
                mma_f16(S[2 * sp],     qf, kf[0], kf[2]);
                mma_f16(S[2 * sp + 1], qf, kf[1], kf[3]);
            }
        }

        // ---- softmax (no max): P = exp2(S*SCALE) ----
#pragma unroll
        for (int j = 0; j < 16; j++) {
            float p0 = ex2f(S[j][0] * SCALE);
            float p1 = ex2f(S[j][1] * SCALE);
            float p2 = ex2f(S[j][2] * SCALE);
            float p3 = ex2f(S[j][3] * SCALE);
            S[j][0] = p0; S[j][1] = p1; S[j][2] = p2; S[j][3] = p3;
            ls0 += p0 + p1;
            ls1 += p2 + p3;
        }

        // ---- GEMM2: O[t][e] += P[t][s] · V[e][s]^T (P single fp16, regs) ----
#pragma unroll
        for (int ks = 0; ks < 8; ks++) {
            const float* pj0 = S[2 * ks];
            const float* pj1 = S[2 * ks + 1];
            uint32_t pf[4];
            {
                __half2 h;
                h = __floats2half2_rn(pj0[0], pj0[1]); pf[0] = *(uint32_t*)&h;
                h = __floats2half2_rn(pj0[2], pj0[3]); pf[1] = *(uint32_t*)&h;
                h = __floats2half2_rn(pj1[0], pj1[1]); pf[2] = *(uint32_t*)&h;
                h = __floats2half2_rn(pj1[2], pj1[3]); pf[3] = *(uint32_t*)&h;
            }
#pragma unroll
            for (int ep = 0; ep < 8; ep++) {
                uint32_t vf[4];
                ldsm4(vf, bV + ep * 4352 + ks * 32);
                mma_f16(O[2 * ep],     pf, vf[0], vf[2]);
                mma_f16(O[2 * ep + 1], pf, vf[1], vf[3]);
            }
        }
    }

    // ---- epilogue ----
    ls0 += __shfl_xor_sync(0xFFFFFFFFu, ls0, 1);
    ls0 += __shfl_xor_sync(0xFFFFFFFFu, ls0, 2);
    ls1 += __shfl_xor_sync(0xFFFFFFFFu, ls1, 1);
    ls1 += __shfl_xor_sync(0xFFFFFFFFu, ls1, 2);
    float inv0 = __frcp_rn(ls0);
    float inv1 = __frcp_rn(ls1);

    __syncthreads();
    float* smT = (float*)(smraw + (base - raw) + SM_K0);   // [128][136] f32 scratch
    {
        int trow = t0 + (lane >> 2);
#pragma unroll
        for (int j = 0; j < 16; j++) {
            int e0 = j * 8 + (lane & 3) * 2;
            smT[e0 * RSTRIDE + trow]           = O[j][0] * inv0;
            smT[(e0 + 1) * RSTRIDE + trow]     = O[j][1] * inv0;
            smT[e0 * RSTRIDE + trow + 8]       = O[j][2] * inv1;
            smT[(e0 + 1) * RSTRIDE + trow + 8] = O[j][3] * inv1;
        }
    }
    __syncthreads();
    float* ob = out + (size_t)n * C_DIM * HW + tb * 128;
    for (int i = tid; i < 128 * 32; i += THREADS) {
        int e = i >> 5, q4 = (i & 31) * 4;
        *(float4*)(ob + (size_t)e * HW + q4) = *(float4*)(smT + e * RSTRIDE + q4);
    }
}

// ---------------------------------------------------------------------------
extern "C" void kernel_launch(void* const* d_in, const int* in_sizes, int n_in,
                              void* d_out, int out_size) {
    const float* key   = (const float*)d_in[0];
    const float* query = (const float*)d_in[1];
    const float* value = (const float*)d_in[2];
    float* out = (float*)d_out;

    cudaFuncSetAttribute(prep_all, cudaFuncAttributeMaxDynamicSharedMemorySize, 66048);
    cudaFuncSetAttribute(attn_kernel, cudaFuncAttributeMaxDynamicSharedMemorySize, SM_REQ);

    prep_all<<<dim3(NT, N_B, 3), THREADS, 66048>>>(query, key, value);
    attn_kernel<<<dim3(NT, N_B), THREADS, SM_REQ>>>(out);
}